// round 2
// baseline (speedup 1.0000x reference)
#include <cuda_runtime.h>
#include <cstdint>
#include <cstddef>

#define TT_   512
#define BB_   256
#define HID   128
#define GATE  512
#define KSM   96
#define KRG   32

// Scratch (static device globals — allocation is forbidden)
__device__ float g_h1 [(size_t)TT_ * BB_ * 2 * HID];   // layer-0 output [t][b][256]
__device__ float g_g1f[(size_t)TT_ * BB_ * GATE];      // layer-1 fwd precomputed input gates
__device__ float g_h2f[BB_ * HID];                     // layer-1 fwd final h

// ---------------- packed f32x2 helpers ----------------
__device__ __forceinline__ unsigned long long pack2(float lo, float hi) {
    unsigned long long r;
    asm("mov.b64 %0, {%1, %2};" : "=l"(r) : "f"(lo), "f"(hi));
    return r;
}
__device__ __forceinline__ unsigned long long dup2(float v) {
    unsigned long long r;
    asm("mov.b64 %0, {%1, %1};" : "=l"(r) : "f"(v));
    return r;
}
__device__ __forceinline__ void unpack2(unsigned long long v, float& lo, float& hi) {
    asm("mov.b64 {%0, %1}, %2;" : "=f"(lo), "=f"(hi) : "l"(v));
}
__device__ __forceinline__ void ffma2(unsigned long long& d, unsigned long long a, unsigned long long b) {
    asm("fma.rn.f32x2 %0, %1, %2, %0;" : "+l"(d) : "l"(a), "l"(b));
}

// ---------------- activations (accurate: ~1e-6, not .approx tanh) ----------------
__device__ __forceinline__ float sigm_f(float x) {
    return __fdividef(1.0f, 1.0f + __expf(-x));
}
__device__ __forceinline__ float tanh_f(float x) {
    float a = fabsf(x);
    float e = __expf(-2.0f * a);
    float r = __fdividef(1.0f - e, 1.0f + e);
    return copysignf(r, x);
}

// =====================================================================================
// Kernel 1: layer-0 bidirectional recurrence.
// grid (64, 2): 64 CTAs per direction, each owns 4 batch rows, 512 threads
// (thread j owns gate column j). Persistent across all 512 time steps.
// =====================================================================================
extern "C" __global__ void __launch_bounds__(512, 1)
lstm_l0(const float* __restrict__ x,
        const float* __restrict__ Wih_f, const float* __restrict__ Whh_f, const float* __restrict__ bv_f,
        const float* __restrict__ Wih_b, const float* __restrict__ Whh_b, const float* __restrict__ bv_b)
{
    extern __shared__ float sm0[];
    float* Wlow = sm0;                    // [KSM][512] k-major
    float* gate = sm0 + KSM * GATE;       // [4][512]
    float* hsm  = gate + 4 * GATE;        // [128][4]  ([k][b]) — 16B rows
    float* xsm  = hsm + HID * 4;          // [2][4][3]

    const int tid = threadIdx.x;
    const int dir = blockIdx.y;
    const int b0  = blockIdx.x * 4;
    const float* __restrict__ Wih = dir ? Wih_b : Wih_f;
    const float* __restrict__ Whh = dir ? Whh_b : Whh_f;
    const float* __restrict__ bv  = dir ? bv_b  : bv_f;

    for (int idx = tid; idx < KSM * GATE; idx += 512) {
        int k = idx >> 9, j = idx & 511;
        Wlow[idx] = Whh[j * HID + k];
    }
    float wreg[KRG];
#pragma unroll
    for (int r = 0; r < KRG; r++) wreg[r] = Whh[tid * HID + KSM + r];

    const float wi0 = Wih[tid * 3 + 0], wi1 = Wih[tid * 3 + 1], wi2 = Wih[tid * 3 + 2];
    const float bias = bv[tid];

    hsm[tid] = 0.0f;                       // 512 == HID*4
    if (tid < 12) {
        int r = tid / 3, i = tid % 3;
        int t0 = dir ? (TT_ - 1) : 0;
        xsm[tid] = x[((size_t)(b0 + r) * TT_ + t0) * 3 + i];
    }
    const int u = tid & 127, bb = tid >> 7;
    float c = 0.0f;
    __syncthreads();

    for (int s = 0; s < TT_; s++) {
        const int tcur = dir ? (TT_ - 1 - s) : s;
        const int pb = s & 1;
        const float* xp = xsm + pb * 12;

        float a0 = fmaf(wi2, xp[2],  fmaf(wi1, xp[1],  fmaf(wi0, xp[0],  bias)));
        float a1 = fmaf(wi2, xp[5],  fmaf(wi1, xp[4],  fmaf(wi0, xp[3],  bias)));
        float a2 = fmaf(wi2, xp[8],  fmaf(wi1, xp[7],  fmaf(wi0, xp[6],  bias)));
        float a3 = fmaf(wi2, xp[11], fmaf(wi1, xp[10], fmaf(wi0, xp[9],  bias)));
        unsigned long long A0 = pack2(a0, a1), A1 = pack2(a2, a3);

        const float* wp = Wlow + tid;
#pragma unroll 8
        for (int k = 0; k < KSM; k++) {
            unsigned long long w2 = dup2(wp[k * GATE]);
            ulonglong2 hh = *reinterpret_cast<const ulonglong2*>(hsm + k * 4);
            ffma2(A0, w2, hh.x);
            ffma2(A1, w2, hh.y);
        }
#pragma unroll
        for (int r = 0; r < KRG; r++) {
            unsigned long long w2 = dup2(wreg[r]);
            ulonglong2 hh = *reinterpret_cast<const ulonglong2*>(hsm + (KSM + r) * 4);
            ffma2(A0, w2, hh.x);
            ffma2(A1, w2, hh.y);
        }
        unpack2(A0, a0, a1); unpack2(A1, a2, a3);
        gate[0 * GATE + tid] = a0;
        gate[1 * GATE + tid] = a1;
        gate[2 * GATE + tid] = a2;
        gate[3 * GATE + tid] = a3;
        __syncthreads();

        {   // cell update: thread -> (u, bb)
            float gi = gate[bb * GATE + u];
            float gf = gate[bb * GATE + u + 128];
            float gg = gate[bb * GATE + u + 256];
            float go = gate[bb * GATE + u + 384];
            c = sigm_f(gf) * c + sigm_f(gi) * tanh_f(gg);
            float h = sigm_f(go) * tanh_f(c);
            hsm[u * 4 + bb] = h;
            g_h1[((size_t)tcur * BB_ + b0 + bb) * (2 * HID) + dir * HID + u] = h;
        }
        if (s + 1 < TT_ && tid < 12) {     // prefetch next x into other buffer
            int r = tid / 3, i = tid % 3;
            int tn = dir ? (TT_ - 2 - s) : (s + 1);
            xsm[(pb ^ 1) * 12 + tid] = x[((size_t)(b0 + r) * TT_ + tn) * 3 + i];
        }
        __syncthreads();
    }
}

// =====================================================================================
// Kernel 2: layer-1 forward input projection GEMM (bias folded):
//   g_g1f[r][j] = h1[r][:] @ W_ih_l1f[j][:]^T + b_l1f[j],  r = t*B+b (131072 rows)
// grid 148 = 4 j-blocks x 37 row-tile walkers; 64-row tiles; FFMA2 inner loop.
// =====================================================================================
#define APITCH 68     // 68*4 = 272 B, multiple of 16 -> LDS.128-able
#define WPITCH 129
extern "C" __global__ void __launch_bounds__(512, 1)
gemm_l1in(const float* __restrict__ W, const float* __restrict__ bias)
{
    extern __shared__ float smg[];
    float* Asm = smg;                    // [256][APITCH] (k-major, row minor)
    float* Wsm = smg + 256 * APITCH;     // [256][WPITCH] (k-major, j minor)

    const int tid  = threadIdx.x;
    const int jblk = blockIdx.x & 3;
    const int tg   = blockIdx.x >> 2;    // 0..36

    for (int idx = tid; idx < 128 * 256; idx += 512) {
        int k = idx & 255, jj = idx >> 8;
        Wsm[k * WPITCH + jj] = W[((jblk << 7) + jj) * 256 + k];
    }

    const int j  = tid & 127;
    const int rg = tid >> 7;             // 4 groups of 16 rows
    const float bj = bias[(jblk << 7) + j];
    const unsigned long long bpack = pack2(bj, bj);

    for (int tile = tg; tile < 2048; tile += 37) {
        const size_t r0 = (size_t)tile * 64;
        __syncthreads();                 // protects Asm reuse (and Wsm on iter 0)
        for (int idx = tid; idx < 64 * 256; idx += 512) {
            int k = idx & 255, row = idx >> 8;
            Asm[k * APITCH + row] = g_h1[(r0 + row) * 256 + k];
        }
        __syncthreads();

        unsigned long long acc[8];
#pragma unroll
        for (int p = 0; p < 8; p++) acc[p] = bpack;

#pragma unroll 4
        for (int k = 0; k < 256; k++) {
            unsigned long long w2 = dup2(Wsm[k * WPITCH + j]);
            const ulonglong2* ap =
                reinterpret_cast<const ulonglong2*>(Asm + k * APITCH + rg * 16);
#pragma unroll
            for (int q = 0; q < 4; q++) {
                ulonglong2 av = ap[q];
                ffma2(acc[2 * q],     w2, av.x);
                ffma2(acc[2 * q + 1], w2, av.y);
            }
        }
#pragma unroll
        for (int p = 0; p < 8; p++) {
            float v0, v1; unpack2(acc[p], v0, v1);
            size_t r = r0 + rg * 16 + 2 * p;
            g_g1f[r * GATE + (jblk << 7) + j]       = v0;
            g_g1f[(r + 1) * GATE + (jblk << 7) + j] = v1;
        }
    }
}

// =====================================================================================
// Kernel 3: layer-1 forward recurrence. grid 128, 2 batch rows per CTA.
// Input gates precomputed in g_g1f. Only final h kept.
// =====================================================================================
extern "C" __global__ void __launch_bounds__(512, 1)
lstm_l1(const float* __restrict__ Whh)
{
    extern __shared__ float sm1[];
    float* Wlow = sm1;                   // [KSM][512]
    float* gate = sm1 + KSM * GATE;      // [2][512]
    float* hsm  = gate + 2 * GATE;       // [128][2]

    const int tid = threadIdx.x;
    const int b0  = blockIdx.x * 2;

    for (int idx = tid; idx < KSM * GATE; idx += 512) {
        int k = idx >> 9, j = idx & 511;
        Wlow[idx] = Whh[j * HID + k];
    }
    float wreg[KRG];
#pragma unroll
    for (int r = 0; r < KRG; r++) wreg[r] = Whh[tid * HID + KSM + r];

    if (tid < HID * 2) hsm[tid] = 0.0f;

    float p0 = g_g1f[(size_t)(b0 + 0) * GATE + tid];   // row t=0, b=b0
    float p1 = g_g1f[(size_t)(b0 + 1) * GATE + tid];

    const int u = tid & 127, bb = tid >> 7;
    const bool docell = tid < 256;
    float c = 0.0f;
    __syncthreads();

    for (int s = 0; s < TT_; s++) {
        unsigned long long A0 = pack2(p0, p1);
        const float* wp = Wlow + tid;
#pragma unroll 8
        for (int k = 0; k < KSM; k++) {
            unsigned long long w2 = dup2(wp[k * GATE]);
            unsigned long long hh = *reinterpret_cast<const unsigned long long*>(hsm + k * 2);
            ffma2(A0, w2, hh);
        }
#pragma unroll
        for (int r = 0; r < KRG; r++) {
            unsigned long long w2 = dup2(wreg[r]);
            unsigned long long hh = *reinterpret_cast<const unsigned long long*>(hsm + (KSM + r) * 2);
            ffma2(A0, w2, hh);
        }
        float a0, a1; unpack2(A0, a0, a1);
        gate[0 * GATE + tid] = a0;
        gate[1 * GATE + tid] = a1;
        __syncthreads();

        if (s + 1 < TT_) {               // prefetch next step's input gates
            p0 = g_g1f[((size_t)(s + 1) * BB_ + b0 + 0) * GATE + tid];
            p1 = g_g1f[((size_t)(s + 1) * BB_ + b0 + 1) * GATE + tid];
        }
        if (docell) {
            float gi = gate[bb * GATE + u];
            float gf = gate[bb * GATE + u + 128];
            float gg = gate[bb * GATE + u + 256];
            float go = gate[bb * GATE + u + 384];
            c = sigm_f(gf) * c + sigm_f(gi) * tanh_f(gg);
            float h = sigm_f(go) * tanh_f(c);
            hsm[u * 2 + bb] = h;
            if (s == TT_ - 1) g_h2f[(b0 + bb) * HID + u] = h;
        }
        __syncthreads();
    }
}

// =====================================================================================
// Kernel 4: layer-1 backward = ONE step from zero state (h2 backward at t=T-1 is the
// reverse scan's first step: c = sigm(i)*tanh(g), h = sigm(o)*tanh(c)), then final FC.
// grid 256: one CTA per batch row; 512 threads (thread j computes gate j).
// =====================================================================================
extern "C" __global__ void __launch_bounds__(512, 1)
final_k(const float* __restrict__ Wihb, const float* __restrict__ bvb,
        const float* __restrict__ Wfc,  const float* __restrict__ bfc,
        float* __restrict__ out)
{
    __shared__ float h1row[256];
    __shared__ float hfr[128];
    __shared__ float gate[512];
    __shared__ float hb[128];

    const int tid = threadIdx.x;
    const int b   = blockIdx.x;

    if (tid < 256)
        h1row[tid] = g_h1[((size_t)(TT_ - 1) * BB_ + b) * 256 + tid];
    else if (tid < 384)
        hfr[tid - 256] = g_h2f[b * HID + (tid - 256)];
    __syncthreads();

    float acc = bvb[tid];
    const float* wr = Wihb + (size_t)tid * 256;
#pragma unroll 8
    for (int k = 0; k < 256; k++) acc = fmaf(h1row[k], wr[k], acc);
    gate[tid] = acc;
    __syncthreads();

    if (tid < 128) {
        float gi = gate[tid];
        float gg = gate[tid + 256];
        float go = gate[tid + 384];
        float c  = sigm_f(gi) * tanh_f(gg);        // f-gate multiplies c0 = 0
        hb[tid]  = sigm_f(go) * tanh_f(c);
    }
    __syncthreads();

    if (tid < 6) {
        float s = bfc[tid];
        const float* wf = Wfc + tid * 256;
#pragma unroll 8
        for (int jj = 0; jj < 128; jj++)
            s = fmaf(hb[jj], wf[128 + jj], fmaf(hfr[jj], wf[jj], s));
        out[b * 6 + tid] = s;
    }
}

// =====================================================================================
extern "C" void kernel_launch(void* const* d_in, const int* in_sizes, int n_in,
                              void* d_out, int out_size)
{
    (void)in_sizes; (void)n_in; (void)out_size;
    const float* x     = (const float*)d_in[0];
    const float* Wih0f = (const float*)d_in[1];
    const float* Whh0f = (const float*)d_in[2];
    const float* b0f   = (const float*)d_in[3];
    const float* Wih0b = (const float*)d_in[4];
    const float* Whh0b = (const float*)d_in[5];
    const float* b0b   = (const float*)d_in[6];
    const float* Wih1f = (const float*)d_in[7];
    const float* Whh1f = (const float*)d_in[8];
    const float* b1f   = (const float*)d_in[9];
    const float* Wih1b = (const float*)d_in[10];
    const float* Whh1b = (const float*)d_in[11];
    const float* b1b   = (const float*)d_in[12];
    const float* Wfc   = (const float*)d_in[13];
    const float* bfc   = (const float*)d_in[14];
    float* out = (float*)d_out;

    const int SM_L0 = (KSM * GATE + 4 * GATE + HID * 4 + 24) * 4;        // 206944 B
    const int SM_G  = (256 * APITCH + 256 * WPITCH) * 4;                 // 201728 B
    const int SM_L1 = (KSM * GATE + 2 * GATE + HID * 2) * 4;             // 201728 B

    cudaFuncSetAttribute(lstm_l0,   cudaFuncAttributeMaxDynamicSharedMemorySize, SM_L0);
    cudaFuncSetAttribute(gemm_l1in, cudaFuncAttributeMaxDynamicSharedMemorySize, SM_G);
    cudaFuncSetAttribute(lstm_l1,   cudaFuncAttributeMaxDynamicSharedMemorySize, SM_L1);

    lstm_l0<<<dim3(64, 2), 512, SM_L0>>>(x, Wih0f, Whh0f, b0f, Wih0b, Whh0b, b0b);
    gemm_l1in<<<148, 512, SM_G>>>(Wih1f, b1f);
    lstm_l1<<<128, 512, SM_L1>>>(Whh1f);
    final_k<<<256, 512>>>(Wih1b, b1b, Wfc, bfc, out);
}